// round 7
// baseline (speedup 1.0000x reference)
#include <cuda_runtime.h>
#include <math_constants.h>

// Problem constants (fixed by setup_inputs)
#define Bq   128
#define Nq   8192
#define Hq   4
#define THREADS 512
#define WARPS   16
#define PPW  (Nq / WARPS)   // 512 points per warp

// Scratch for logits: [B][N] float4 (one logit per head). 16 MB device global.
__device__ float4 g_logits[(size_t)Bq * Nq];

__global__ __launch_bounds__(THREADS, 1)
void mha_mlp_attn_kernel(const float* __restrict__ radar_xy,
                         const float* __restrict__ radar_dir,
                         const float* __restrict__ pts,
                         const float* __restrict__ enc_w1,
                         const float* __restrict__ enc_b1,
                         const float* __restrict__ enc_w2,
                         const float* __restrict__ enc_b2,
                         const float* __restrict__ sc_w1,
                         const float* __restrict__ sc_b1,
                         const float* __restrict__ sc_w2,
                         const float* __restrict__ sc_b2,
                         const float* __restrict__ out_w1,
                         const float* __restrict__ out_b1,
                         const float* __restrict__ out_w2,
                         const float* __restrict__ out_b2,
                         float* __restrict__ out)
{
    __shared__ float sE1[64], sE2[64], sBE[64];          // encoder L1: px,py coeffs + per-b base
    __shared__ float sA[4][64], sBw[4][64], sC[4][64];   // score L1 per head
    __shared__ float sW2[4][64];                          // score L2 per head
    __shared__ float sWmax[WARPS][4];
    __shared__ float sMax[4];
    __shared__ float sRed[WARPS][4][64];                  // per-warp pooled partials (16 KB)
    __shared__ float sWsum[WARPS][4];
    __shared__ float sSum[4];
    __shared__ float sPooled[4][64];
    __shared__ float sCtx[256];
    __shared__ float sO[64];

    const int b    = blockIdx.x;
    const int tid  = threadIdx.x;
    const int warp = tid >> 5;
    const int lane = tid & 31;

    const float r0 = radar_xy[b*2+0], r1 = radar_xy[b*2+1];
    const float r2 = radar_dir[b*2+0], r3 = radar_dir[b*2+1];

    // ---- Stage weights + per-batch bases into shared ----
    if (tid < 64) {
        const int j = tid;
        sE1[j] = enc_w1[4*64 + j];
        sE2[j] = enc_w1[5*64 + j];
        sBE[j] = enc_b1[j] + r0*enc_w1[0*64+j] + r1*enc_w1[1*64+j]
                           + r2*enc_w1[2*64+j] + r3*enc_w1[3*64+j];
    }
    if (tid < 256) {
        const int h = tid >> 6, j = tid & 63;
        const float* w = sc_w1 + (size_t)h * 6 * 64;
        sA [h][j] = w[4*64 + j];
        sBw[h][j] = w[5*64 + j];
        sC [h][j] = sc_b1[h*64+j] + r0*w[0*64+j] + r1*w[1*64+j]
                                  + r2*w[2*64+j] + r3*w[3*64+j];
        sW2[h][j] = sc_w2[h*64 + j];
    }
    __syncthreads();

    // ============ Pass 1: per-point logits for 4 heads + running max ============
    // Lane layout: head h = lane>>3, sub-lane s = lane&7 owns js = s*8 .. s*8+7.
    {
        const int h = lane >> 3, s = lane & 7;
        float aw[8], bw[8], cw[8], vw[8];
        #pragma unroll
        for (int k = 0; k < 8; k++) {
            const int j = s*8 + k;
            aw[k] = sA[h][j]; bw[k] = sBw[h][j]; cw[k] = sC[h][j]; vw[k] = sW2[h][j];
        }
        const float b2h = sc_b2[h];
        float m = -CUDART_INF_F;

        const float2* P = (const float2*)pts + (size_t)b * Nq + warp * PPW;
        float* L = (float*)(g_logits + (size_t)b * Nq + warp * PPW);

        #pragma unroll 2
        for (int i = 0; i < PPW; i++) {
            const float2 p = __ldg(P + i);
            float acc0 = 0.f, acc1 = 0.f;
            #pragma unroll
            for (int k = 0; k < 8; k += 2) {
                float t0 = fmaf(p.y, bw[k],   fmaf(p.x, aw[k],   cw[k]));
                acc0 = fmaf(fmaxf(t0, 0.f), vw[k],   acc0);
                float t1 = fmaf(p.y, bw[k+1], fmaf(p.x, aw[k+1], cw[k+1]));
                acc1 = fmaf(fmaxf(t1, 0.f), vw[k+1], acc1);
            }
            float acc = acc0 + acc1;
            acc += __shfl_xor_sync(0xffffffffu, acc, 1);
            acc += __shfl_xor_sync(0xffffffffu, acc, 2);
            acc += __shfl_xor_sync(0xffffffffu, acc, 4);
            acc += b2h;                       // full logit on all 8 lanes of group
            if (s == 0) {
                L[i*4 + h] = acc;             // 4 lanes -> one 16B transaction
                m = fmaxf(m, acc);
            }
        }
        if (s == 0) sWmax[warp][h] = m;
    }
    __syncthreads();
    if (tid < 4) {
        float mm = -CUDART_INF_F;
        #pragma unroll
        for (int w = 0; w < WARPS; w++) mm = fmaxf(mm, sWmax[w][tid]);
        sMax[tid] = mm;
    }
    __syncthreads();

    // ============ Pass 2: exp weights + pooled h1 accumulation ============
    // Lane owns feature lanes j0=lane, j1=lane+32; own head = lane&3 for exp.
    {
        const int hw = lane & 3;
        const float mOwn = sMax[hw];
        const int j0 = lane, j1 = lane + 32;
        const float e10 = sE1[j0], e11 = sE1[j1];
        const float e20 = sE2[j0], e21 = sE2[j1];
        const float be0 = sBE[j0], be1 = sBE[j1];
        float p00=0.f,p01=0.f,p10=0.f,p11=0.f,p20=0.f,p21=0.f,p30=0.f,p31=0.f;
        float sOwn = 0.f;

        const float2* P  = (const float2*)pts + (size_t)b * Nq + warp * PPW;
        const float4* L4 = g_logits + (size_t)b * Nq + warp * PPW;

        #pragma unroll 2
        for (int i = 0; i < PPW; i++) {
            const float2 p  = __ldg(P + i);
            const float4 lg = L4[i];                 // broadcast LDG.128
            float lown = lg.x;
            if (hw == 1) lown = lg.y;
            if (hw == 2) lown = lg.z;
            if (hw == 3) lown = lg.w;
            const float wOwn = __expf(lown - mOwn);
            sOwn += wOwn;
            const float w0 = __shfl_sync(0xffffffffu, wOwn, 0, 4);
            const float w1 = __shfl_sync(0xffffffffu, wOwn, 1, 4);
            const float w2v= __shfl_sync(0xffffffffu, wOwn, 2, 4);
            const float w3 = __shfl_sync(0xffffffffu, wOwn, 3, 4);

            const float h0  = fmaxf(fmaf(p.y, e20, fmaf(p.x, e10, be0)), 0.f);
            const float h1v = fmaxf(fmaf(p.y, e21, fmaf(p.x, e11, be1)), 0.f);

            p00 = fmaf(w0,  h0, p00);  p01 = fmaf(w0,  h1v, p01);
            p10 = fmaf(w1,  h0, p10);  p11 = fmaf(w1,  h1v, p11);
            p20 = fmaf(w2v, h0, p20);  p21 = fmaf(w2v, h1v, p21);
            p30 = fmaf(w3,  h0, p30);  p31 = fmaf(w3,  h1v, p31);
        }
        sRed[warp][0][j0] = p00; sRed[warp][0][j1] = p01;
        sRed[warp][1][j0] = p10; sRed[warp][1][j1] = p11;
        sRed[warp][2][j0] = p20; sRed[warp][2][j1] = p21;
        sRed[warp][3][j0] = p30; sRed[warp][3][j1] = p31;
        if (lane < 4) sWsum[warp][lane] = sOwn;   // identical across 4-lane groups
    }
    __syncthreads();

    // ============ Finalize: normalize, contexts @ enc_w2, output MLP ============
    if (tid < 4) {
        float ss = 0.f;
        #pragma unroll
        for (int w = 0; w < WARPS; w++) ss += sWsum[w][tid];
        sSum[tid] = ss;
    }
    __syncthreads();
    if (tid < 256) {
        const int h = tid >> 6, j = tid & 63;
        float acc = 0.f;
        #pragma unroll
        for (int w = 0; w < WARPS; w++) acc += sRed[w][h][j];
        sPooled[h][j] = acc / sSum[h];
    }
    __syncthreads();
    if (tid < 256) {
        const int h = tid >> 6, d = tid & 63;
        float acc = enc_b2[d];
        #pragma unroll 8
        for (int k = 0; k < 64; k++)
            acc = fmaf(sPooled[h][k], enc_w2[k*64 + d], acc);
        sCtx[h*64 + d] = acc;   // head-major, matching reshape(B, H*HID)
    }
    __syncthreads();
    if (tid < 64) {
        float acc = out_b1[tid];
        #pragma unroll 8
        for (int c = 0; c < 256; c++)
            acc = fmaf(sCtx[c], out_w1[c*64 + tid], acc);
        sO[tid] = fmaxf(acc, 0.f);
    }
    __syncthreads();
    if (tid < 32) {
        float v = sO[tid]*out_w2[tid] + sO[tid+32]*out_w2[tid+32];
        #pragma unroll
        for (int o = 16; o > 0; o >>= 1)
            v += __shfl_xor_sync(0xffffffffu, v, o);
        if (tid == 0) out[b] = v + out_b2[0];
    }
}

extern "C" void kernel_launch(void* const* d_in, const int* in_sizes, int n_in,
                              void* d_out, int out_size)
{
    const float* radar_xy  = (const float*)d_in[0];
    const float* radar_dir = (const float*)d_in[1];
    const float* pts       = (const float*)d_in[2];
    const float* enc_w1    = (const float*)d_in[3];
    const float* enc_b1    = (const float*)d_in[4];
    const float* enc_w2    = (const float*)d_in[5];
    const float* enc_b2    = (const float*)d_in[6];
    const float* sc_w1     = (const float*)d_in[7];
    const float* sc_b1     = (const float*)d_in[8];
    const float* sc_w2     = (const float*)d_in[9];
    const float* sc_b2     = (const float*)d_in[10];
    const float* out_w1    = (const float*)d_in[11];
    const float* out_b1    = (const float*)d_in[12];
    const float* out_w2    = (const float*)d_in[13];
    const float* out_b2    = (const float*)d_in[14];
    float* out = (float*)d_out;

    mha_mlp_attn_kernel<<<Bq, THREADS>>>(
        radar_xy, radar_dir, pts,
        enc_w1, enc_b1, enc_w2, enc_b2,
        sc_w1, sc_b1, sc_w2, sc_b2,
        out_w1, out_b1, out_w2, out_b2,
        out);
}

// round 8
// speedup vs baseline: 1.3789x; 1.3789x over previous
#include <cuda_runtime.h>
#include <math_constants.h>

// Problem constants (fixed by setup_inputs)
#define Bq   128
#define Nq   8192
#define Hq   4
#define THREADS 1024
#define WARPS   32
#define PPW  (Nq / WARPS)   // 256 points per warp

// Scratch for logits: [B][N] float4 (one logit per head). 16 MB device global.
__device__ float4 g_logits[(size_t)Bq * Nq];

// ---- Blackwell packed fp32x2 helpers (FFMA2 only reachable via PTX) ----
__device__ __forceinline__ unsigned long long pk2(float lo, float hi) {
    unsigned long long r;
    asm("mov.b64 %0, {%1, %2};" : "=l"(r) : "f"(lo), "f"(hi));
    return r;
}
__device__ __forceinline__ unsigned long long ffma2(unsigned long long a,
                                                    unsigned long long b,
                                                    unsigned long long c) {
    unsigned long long d;
    asm("fma.rn.f32x2 %0, %1, %2, %3;" : "=l"(d) : "l"(a), "l"(b), "l"(c));
    return d;
}
__device__ __forceinline__ float2 upk2(unsigned long long v) {
    float2 f;
    asm("mov.b64 {%0, %1}, %2;" : "=f"(f.x), "=f"(f.y) : "l"(v));
    return f;
}

__global__ __launch_bounds__(THREADS, 1)
void mha_mlp_attn_kernel(const float* __restrict__ radar_xy,
                         const float* __restrict__ radar_dir,
                         const float* __restrict__ pts,
                         const float* __restrict__ enc_w1,
                         const float* __restrict__ enc_b1,
                         const float* __restrict__ enc_w2,
                         const float* __restrict__ enc_b2,
                         const float* __restrict__ sc_w1,
                         const float* __restrict__ sc_b1,
                         const float* __restrict__ sc_w2,
                         const float* __restrict__ sc_b2,
                         const float* __restrict__ out_w1,
                         const float* __restrict__ out_b1,
                         const float* __restrict__ out_w2,
                         const float* __restrict__ out_b2,
                         float* __restrict__ out)
{
    __shared__ float sE1[64], sE2[64], sBE[64];          // encoder L1: px,py coeffs + per-b base
    __shared__ float sA[4][64], sBw[4][64], sC[4][64];   // score L1 per head
    __shared__ float sW2[4][64];                          // score L2 per head
    __shared__ float sWmax[WARPS][4];
    __shared__ float sMax[4];
    __shared__ float sRed[WARPS][4][64];                  // per-warp pooled partials (32 KB)
    __shared__ float sWsum[WARPS][4];
    __shared__ float sSum[4];
    __shared__ float sPooled[4][64];
    __shared__ float sCtx[256];
    __shared__ float sO[64];

    const int b    = blockIdx.x;
    const int tid  = threadIdx.x;
    const int warp = tid >> 5;
    const int lane = tid & 31;

    const float r0 = radar_xy[b*2+0], r1 = radar_xy[b*2+1];
    const float r2 = radar_dir[b*2+0], r3 = radar_dir[b*2+1];

    // ---- Stage weights + per-batch bases into shared ----
    if (tid < 64) {
        const int j = tid;
        sE1[j] = enc_w1[4*64 + j];
        sE2[j] = enc_w1[5*64 + j];
        sBE[j] = enc_b1[j] + r0*enc_w1[0*64+j] + r1*enc_w1[1*64+j]
                           + r2*enc_w1[2*64+j] + r3*enc_w1[3*64+j];
    }
    if (tid >= 512 && tid < 768) {
        const int t = tid - 512;
        const int h = t >> 6, j = t & 63;
        const float* w = sc_w1 + (size_t)h * 6 * 64;
        sA [h][j] = w[4*64 + j];
        sBw[h][j] = w[5*64 + j];
        sC [h][j] = sc_b1[h*64+j] + r0*w[0*64+j] + r1*w[1*64+j]
                                  + r2*w[2*64+j] + r3*w[3*64+j];
        sW2[h][j] = sc_w2[h*64 + j];
    }
    __syncthreads();

    // ============ Pass 1: per-point logits for 4 heads + running max ============
    // Lane layout: head h = lane>>3, sub-lane s = lane&7 owns js = s*8 .. s*8+7.
    // Inner math packed as fp32x2 (FFMA2): j-pairs in 64-bit register pairs.
    {
        const int h = lane >> 3, s = lane & 7;
        unsigned long long aw[4], bw[4], cw[4], vw[4];
        #pragma unroll
        for (int k = 0; k < 4; k++) {
            const int j = s*8 + k*2;
            aw[k] = pk2(sA [h][j], sA [h][j+1]);
            bw[k] = pk2(sBw[h][j], sBw[h][j+1]);
            cw[k] = pk2(sC [h][j], sC [h][j+1]);
            vw[k] = pk2(sW2[h][j], sW2[h][j+1]);
        }
        const float b2h = sc_b2[h];
        float m = -CUDART_INF_F;

        const float2* P = (const float2*)pts + (size_t)b * Nq + warp * PPW;
        float* L = (float*)(g_logits + (size_t)b * Nq + warp * PPW);

        #pragma unroll 2
        for (int i = 0; i < PPW; i++) {
            const float2 p = __ldg(P + i);
            const unsigned long long pxx = pk2(p.x, p.x);
            const unsigned long long pyy = pk2(p.y, p.y);
            unsigned long long acc2 = 0ull;   // (0.f, 0.f)
            #pragma unroll
            for (int k = 0; k < 4; k++) {
                unsigned long long t = ffma2(pyy, bw[k], ffma2(pxx, aw[k], cw[k]));
                float2 tf = upk2(t);
                tf.x = fmaxf(tf.x, 0.f);
                tf.y = fmaxf(tf.y, 0.f);
                acc2 = ffma2(pk2(tf.x, tf.y), vw[k], acc2);
            }
            const float2 a2 = upk2(acc2);
            float acc = a2.x + a2.y;
            acc += __shfl_xor_sync(0xffffffffu, acc, 1);
            acc += __shfl_xor_sync(0xffffffffu, acc, 2);
            acc += __shfl_xor_sync(0xffffffffu, acc, 4);
            acc += b2h;                       // full logit on all 8 lanes of group
            if (s == 0) {
                L[i*4 + h] = acc;             // 4 lanes -> one 16B transaction
                m = fmaxf(m, acc);
            }
        }
        if (s == 0) sWmax[warp][h] = m;
    }
    __syncthreads();
    if (tid < 4) {
        float mm = -CUDART_INF_F;
        #pragma unroll
        for (int w = 0; w < WARPS; w++) mm = fmaxf(mm, sWmax[w][tid]);
        sMax[tid] = mm;
    }
    __syncthreads();

    // ============ Pass 2: exp weights + pooled h1 accumulation ============
    // Lane owns feature lanes j0=lane, j1=lane+32; own head = lane&3 for exp.
    {
        const int hw = lane & 3;
        const float mOwn = sMax[hw];
        const int j0 = lane, j1 = lane + 32;
        const float e10 = sE1[j0], e11 = sE1[j1];
        const float e20 = sE2[j0], e21 = sE2[j1];
        const float be0 = sBE[j0], be1 = sBE[j1];
        float p00=0.f,p01=0.f,p10=0.f,p11=0.f,p20=0.f,p21=0.f,p30=0.f,p31=0.f;
        float sOwn = 0.f;

        const float2* P  = (const float2*)pts + (size_t)b * Nq + warp * PPW;
        const float4* L4 = g_logits + (size_t)b * Nq + warp * PPW;

        #pragma unroll 2
        for (int i = 0; i < PPW; i++) {
            const float2 p  = __ldg(P + i);
            const float4 lg = L4[i];                 // broadcast LDG.128
            float lown = lg.x;
            if (hw == 1) lown = lg.y;
            if (hw == 2) lown = lg.z;
            if (hw == 3) lown = lg.w;
            const float wOwn = __expf(lown - mOwn);
            sOwn += wOwn;
            const float w0 = __shfl_sync(0xffffffffu, wOwn, 0, 4);
            const float w1 = __shfl_sync(0xffffffffu, wOwn, 1, 4);
            const float w2v= __shfl_sync(0xffffffffu, wOwn, 2, 4);
            const float w3 = __shfl_sync(0xffffffffu, wOwn, 3, 4);

            const float h0  = fmaxf(fmaf(p.y, e20, fmaf(p.x, e10, be0)), 0.f);
            const float h1v = fmaxf(fmaf(p.y, e21, fmaf(p.x, e11, be1)), 0.f);

            p00 = fmaf(w0,  h0, p00);  p01 = fmaf(w0,  h1v, p01);
            p10 = fmaf(w1,  h0, p10);  p11 = fmaf(w1,  h1v, p11);
            p20 = fmaf(w2v, h0, p20);  p21 = fmaf(w2v, h1v, p21);
            p30 = fmaf(w3,  h0, p30);  p31 = fmaf(w3,  h1v, p31);
        }
        sRed[warp][0][j0] = p00; sRed[warp][0][j1] = p01;
        sRed[warp][1][j0] = p10; sRed[warp][1][j1] = p11;
        sRed[warp][2][j0] = p20; sRed[warp][2][j1] = p21;
        sRed[warp][3][j0] = p30; sRed[warp][3][j1] = p31;
        if (lane < 4) sWsum[warp][lane] = sOwn;   // identical across 4-lane groups
    }
    __syncthreads();

    // ============ Finalize: normalize, contexts @ enc_w2, output MLP ============
    if (tid < 4) {
        float ss = 0.f;
        #pragma unroll
        for (int w = 0; w < WARPS; w++) ss += sWsum[w][tid];
        sSum[tid] = ss;
    }
    __syncthreads();
    if (tid < 256) {
        const int h = tid >> 6, j = tid & 63;
        float acc = 0.f;
        #pragma unroll
        for (int w = 0; w < WARPS; w++) acc += sRed[w][h][j];
        sPooled[h][j] = acc / sSum[h];
    }
    __syncthreads();
    if (tid < 256) {
        const int h = tid >> 6, d = tid & 63;
        float acc = enc_b2[d];
        #pragma unroll 8
        for (int k = 0; k < 64; k++)
            acc = fmaf(sPooled[h][k], enc_w2[k*64 + d], acc);
        sCtx[h*64 + d] = acc;   // head-major, matching reshape(B, H*HID)
    }
    __syncthreads();
    if (tid < 64) {
        float acc = out_b1[tid];
        #pragma unroll 8
        for (int c = 0; c < 256; c++)
            acc = fmaf(sCtx[c], out_w1[c*64 + tid], acc);
        sO[tid] = fmaxf(acc, 0.f);
    }
    __syncthreads();
    if (tid < 32) {
        float v = sO[tid]*out_w2[tid] + sO[tid+32]*out_w2[tid+32];
        #pragma unroll
        for (int o = 16; o > 0; o >>= 1)
            v += __shfl_xor_sync(0xffffffffu, v, o);
        if (tid == 0) out[b] = v + out_b2[0];
    }
}

extern "C" void kernel_launch(void* const* d_in, const int* in_sizes, int n_in,
                              void* d_out, int out_size)
{
    const float* radar_xy  = (const float*)d_in[0];
    const float* radar_dir = (const float*)d_in[1];
    const float* pts       = (const float*)d_in[2];
    const float* enc_w1    = (const float*)d_in[3];
    const float* enc_b1    = (const float*)d_in[4];
    const float* enc_w2    = (const float*)d_in[5];
    const float* enc_b2    = (const float*)d_in[6];
    const float* sc_w1     = (const float*)d_in[7];
    const float* sc_b1     = (const float*)d_in[8];
    const float* sc_w2     = (const float*)d_in[9];
    const float* sc_b2     = (const float*)d_in[10];
    const float* out_w1    = (const float*)d_in[11];
    const float* out_b1    = (const float*)d_in[12];
    const float* out_w2    = (const float*)d_in[13];
    const float* out_b2    = (const float*)d_in[14];
    float* out = (float*)d_out;

    mha_mlp_attn_kernel<<<Bq, THREADS>>>(
        radar_xy, radar_dir, pts,
        enc_w1, enc_b1, enc_w2, enc_b2,
        sc_w1, sc_b1, sc_w2, sc_b2,
        out_w1, out_b1, out_w2, out_b2,
        out);
}

// round 9
// speedup vs baseline: 1.9392x; 1.4064x over previous
#include <cuda_runtime.h>
#include <math_constants.h>

// Problem constants (fixed by setup_inputs)
#define Bq      128
#define Nq      8192
#define THREADS 1024
#define WARPS   32
#define PPW     (Nq / WARPS)   // 256 points per warp
#define NBATCH  (PPW / 4)      // 64 batches of 4 points

typedef unsigned long long ull;

// ---- Blackwell packed fp32x2 helpers (FFMA2 only reachable via PTX) ----
static __device__ __forceinline__ ull pk2(float lo, float hi) {
    ull r; asm("mov.b64 %0, {%1, %2};" : "=l"(r) : "f"(lo), "f"(hi)); return r;
}
static __device__ __forceinline__ ull ffma2(ull a, ull b, ull c) {
    ull d; asm("fma.rn.f32x2 %0, %1, %2, %3;" : "=l"(d) : "l"(a), "l"(b), "l"(c)); return d;
}
static __device__ __forceinline__ float2 upk2(ull v) {
    float2 f; asm("mov.b64 {%0, %1}, %2;" : "=f"(f.x), "=f"(f.y) : "l"(v)); return f;
}
static __device__ __forceinline__ ull relu2(ull v) {
    float2 f = upk2(v);
    return pk2(fmaxf(f.x, 0.f), fmaxf(f.y, 0.f));
}

#define LOG2E 1.4426950408889634f

__global__ __launch_bounds__(THREADS, 1)
void mha_fused_kernel(const float* __restrict__ radar_xy,
                      const float* __restrict__ radar_dir,
                      const float* __restrict__ pts,
                      const float* __restrict__ enc_w1,
                      const float* __restrict__ enc_b1,
                      const float* __restrict__ enc_w2,
                      const float* __restrict__ enc_b2,
                      const float* __restrict__ sc_w1,
                      const float* __restrict__ sc_b1,
                      const float* __restrict__ sc_w2,
                      const float* __restrict__ sc_b2,
                      const float* __restrict__ out_w1,
                      const float* __restrict__ out_b1,
                      const float* __restrict__ out_w2,
                      const float* __restrict__ out_b2,
                      float* __restrict__ out)
{
    // Score-net weights, packed u64 per (k, lane=h*8+s): conflict-free LDS
    __shared__ ull        sAW[4][32], sBW[4][32];
    __shared__ ulonglong2 sCV[4][32];                // (c-pair, v-pair) -> one LDS.128
    __shared__ ull        sE1p[32], sE2p[32], sBEp[32];  // encoder packed (j, j+32)
    __shared__ float4     sWexp[2][WARPS][4];        // per-warp softmax-weight broadcast (dbl buf)
    __shared__ float      sRed[WARPS][4][64];        // per-warp pooled partials
    __shared__ float      sWsum[WARPS][4];
    __shared__ float      sSum[4];
    __shared__ float      sPooled[4][64];
    __shared__ float      sCtx[256];
    __shared__ float      sO[64];

    const int b    = blockIdx.x;
    const int tid  = threadIdx.x;
    const int warp = tid >> 5;
    const int lane = tid & 31;

    const float r0 = radar_xy[b*2+0], r1 = radar_xy[b*2+1];
    const float r2 = radar_dir[b*2+0], r3 = radar_dir[b*2+1];

    // ---------------- Staging ----------------
    if (tid < 128) {
        // sCV[k][hs] = (packed per-batch bias pair, packed score-w2 pair)
        const int k = tid >> 5, hs = tid & 31;
        const int h = hs >> 3, j = (hs & 7) * 8 + k * 2;
        const float* w = sc_w1 + (size_t)h * 384;
        const float c0 = sc_b1[h*64+j]   + r0*w[j]   + r1*w[64+j]   + r2*w[128+j]   + r3*w[192+j];
        const float c1 = sc_b1[h*64+j+1] + r0*w[j+1] + r1*w[64+j+1] + r2*w[128+j+1] + r3*w[192+j+1];
        ulonglong2 cv;
        cv.x = pk2(c0, c1);
        cv.y = pk2(sc_w2[h*64+j], sc_w2[h*64+j+1]);
        sCV[k][hs] = cv;
    } else if (tid < 224) {
        const int idx = tid - 128, arr = idx >> 5, l = idx & 31;
        if (arr == 0)      sE1p[l] = pk2(enc_w1[256+l], enc_w1[256+l+32]);
        else if (arr == 1) sE2p[l] = pk2(enc_w1[320+l], enc_w1[320+l+32]);
        else {
            const float b0 = enc_b1[l]    + r0*enc_w1[l]    + r1*enc_w1[64+l]
                                          + r2*enc_w1[128+l] + r3*enc_w1[192+l];
            const float b1 = enc_b1[l+32] + r0*enc_w1[l+32] + r1*enc_w1[64+l+32]
                                          + r2*enc_w1[128+l+32] + r3*enc_w1[192+l+32];
            sBEp[l] = pk2(b0, b1);
        }
    } else if (tid >= 256 && tid < 512) {
        const int idx = tid - 256, arr = idx >> 7, k = (idx >> 5) & 3, hs = idx & 31;
        const int h = hs >> 3, j = (hs & 7) * 8 + k * 2;
        const float* w = sc_w1 + (size_t)h * 384 + (arr ? 320 : 256);  // row4=px, row5=py
        const ull v = pk2(w[j], w[j+1]);
        if (arr == 0) sAW[k][hs] = v; else sBW[k][hs] = v;
    }
    __syncthreads();

    // ---------------- Per-lane constants ----------------
    const int h = lane >> 3, s = lane & 7;
    const float b2l = sc_b2[h] * LOG2E;              // folded into exp2
    // After the butterfly, lane s holds point p(s) = (s&1)*2 + ((s>>1)&1)
    const int pOwnH = (((s & 1) << 1) + ((s >> 1) & 1)) * 4 + h;
    const bool sel1 = (s & 1) != 0, sel2 = (s & 2) != 0;

    const ull aw0 = sAW[0][lane], aw1 = sAW[1][lane], aw2 = sAW[2][lane], aw3 = sAW[3][lane];
    const ull bw0 = sBW[0][lane], bw1 = sBW[1][lane], bw2 = sBW[2][lane], bw3 = sBW[3][lane];
    const ull e1p = sE1p[lane], e2p = sE2p[lane], bep = sBEp[lane];

    float p00=0.f,p01=0.f,p10=0.f,p11=0.f,p20=0.f,p21=0.f,p30=0.f,p31=0.f;
    float sOwn = 0.f;

    const float4* P4 = reinterpret_cast<const float4*>(pts)
                     + (((size_t)b * Nq + (size_t)warp * PPW) >> 1);
    float* wslot = &(reinterpret_cast<float*>(&sWexp[0][warp][0]))[pOwnH];

    // ---------------- Fused main loop: 4 points per iteration ----------------
    #pragma unroll 1
    for (int i = 0; i < NBATCH; i++) {
        const float4 q0 = __ldg(P4 + 2*i);
        const float4 q1 = __ldg(P4 + 2*i + 1);
        const ull px0 = pk2(q0.x,q0.x), py0 = pk2(q0.y,q0.y);
        const ull px1 = pk2(q0.z,q0.z), py1 = pk2(q0.w,q0.w);
        const ull px2 = pk2(q1.x,q1.x), py2 = pk2(q1.y,q1.y);
        const ull px3 = pk2(q1.z,q1.z), py3 = pk2(q1.w,q1.w);

        // --- logits: 8-j slice per lane, 4 points, packed fp32x2 ---
        ull ac0, ac1, ac2, ac3;
        {
            ulonglong2 cv = sCV[0][lane];
            ac0 = ffma2(relu2(ffma2(py0,bw0, ffma2(px0,aw0, cv.x))), cv.y, 0ull);
            ac1 = ffma2(relu2(ffma2(py1,bw0, ffma2(px1,aw0, cv.x))), cv.y, 0ull);
            ac2 = ffma2(relu2(ffma2(py2,bw0, ffma2(px2,aw0, cv.x))), cv.y, 0ull);
            ac3 = ffma2(relu2(ffma2(py3,bw0, ffma2(px3,aw0, cv.x))), cv.y, 0ull);
            cv = sCV[1][lane];
            ac0 = ffma2(relu2(ffma2(py0,bw1, ffma2(px0,aw1, cv.x))), cv.y, ac0);
            ac1 = ffma2(relu2(ffma2(py1,bw1, ffma2(px1,aw1, cv.x))), cv.y, ac1);
            ac2 = ffma2(relu2(ffma2(py2,bw1, ffma2(px2,aw1, cv.x))), cv.y, ac2);
            ac3 = ffma2(relu2(ffma2(py3,bw1, ffma2(px3,aw1, cv.x))), cv.y, ac3);
            cv = sCV[2][lane];
            ac0 = ffma2(relu2(ffma2(py0,bw2, ffma2(px0,aw2, cv.x))), cv.y, ac0);
            ac1 = ffma2(relu2(ffma2(py1,bw2, ffma2(px1,aw2, cv.x))), cv.y, ac1);
            ac2 = ffma2(relu2(ffma2(py2,bw2, ffma2(px2,aw2, cv.x))), cv.y, ac2);
            ac3 = ffma2(relu2(ffma2(py3,bw2, ffma2(px3,aw2, cv.x))), cv.y, ac3);
            cv = sCV[3][lane];
            ac0 = ffma2(relu2(ffma2(py0,bw3, ffma2(px0,aw3, cv.x))), cv.y, ac0);
            ac1 = ffma2(relu2(ffma2(py1,bw3, ffma2(px1,aw3, cv.x))), cv.y, ac1);
            ac2 = ffma2(relu2(ffma2(py2,bw3, ffma2(px2,aw3, cv.x))), cv.y, ac2);
            ac3 = ffma2(relu2(ffma2(py3,bw3, ffma2(px3,aw3, cv.x))), cv.y, ac3);
        }
        float2 t;
        t = upk2(ac0); float a0 = t.x + t.y;
        t = upk2(ac1); float a1 = t.x + t.y;
        t = upk2(ac2); float a2 = t.x + t.y;
        t = upk2(ac3); float a3 = t.x + t.y;

        // --- batched butterfly over 8 lanes: 4 shfl / 4 points ---
        const float r0s = __shfl_xor_sync(0xffffffffu, sel1 ? a0 : a2, 1);
        const float r1s = __shfl_xor_sync(0xffffffffu, sel1 ? a1 : a3, 1);
        a0 = (sel1 ? a2 : a0) + r0s;
        a1 = (sel1 ? a3 : a1) + r1s;
        const float r2s = __shfl_xor_sync(0xffffffffu, sel2 ? a0 : a1, 2);
        float v = (sel2 ? a1 : a0) + r2s;
        v += __shfl_xor_sync(0xffffffffu, v, 4);

        // --- exp (no max-sub; softmax normalized at the end) ---
        const float w = exp2f(fmaf(v, LOG2E, b2l));
        sOwn += w;                    // each point counted twice per 8-group (x0.5 later)

        // --- broadcast 16 weights (4 pts x 4 heads) via smem, double-buffered ---
        const int buf = i & 1;
        wslot[buf * (WARPS * 16)] = w;
        __syncwarp();
        const float4 wv0 = sWexp[buf][warp][0];
        const float4 wv1 = sWexp[buf][warp][1];
        const float4 wv2 = sWexp[buf][warp][2];
        const float4 wv3 = sWexp[buf][warp][3];

        // --- pooled accumulation: lane owns features (lane, lane+32) x 4 heads ---
        float2 h2;
        h2 = upk2(relu2(ffma2(py0, e2p, ffma2(px0, e1p, bep))));
        p00 = fmaf(wv0.x, h2.x, p00); p01 = fmaf(wv0.x, h2.y, p01);
        p10 = fmaf(wv0.y, h2.x, p10); p11 = fmaf(wv0.y, h2.y, p11);
        p20 = fmaf(wv0.z, h2.x, p20); p21 = fmaf(wv0.z, h2.y, p21);
        p30 = fmaf(wv0.w, h2.x, p30); p31 = fmaf(wv0.w, h2.y, p31);
        h2 = upk2(relu2(ffma2(py1, e2p, ffma2(px1, e1p, bep))));
        p00 = fmaf(wv1.x, h2.x, p00); p01 = fmaf(wv1.x, h2.y, p01);
        p10 = fmaf(wv1.y, h2.x, p10); p11 = fmaf(wv1.y, h2.y, p11);
        p20 = fmaf(wv1.z, h2.x, p20); p21 = fmaf(wv1.z, h2.y, p21);
        p30 = fmaf(wv1.w, h2.x, p30); p31 = fmaf(wv1.w, h2.y, p31);
        h2 = upk2(relu2(ffma2(py2, e2p, ffma2(px2, e1p, bep))));
        p00 = fmaf(wv2.x, h2.x, p00); p01 = fmaf(wv2.x, h2.y, p01);
        p10 = fmaf(wv2.y, h2.x, p10); p11 = fmaf(wv2.y, h2.y, p11);
        p20 = fmaf(wv2.z, h2.x, p20); p21 = fmaf(wv2.z, h2.y, p21);
        p30 = fmaf(wv2.w, h2.x, p30); p31 = fmaf(wv2.w, h2.y, p31);
        h2 = upk2(relu2(ffma2(py3, e2p, ffma2(px3, e1p, bep))));
        p00 = fmaf(wv3.x, h2.x, p00); p01 = fmaf(wv3.x, h2.y, p01);
        p10 = fmaf(wv3.y, h2.x, p10); p11 = fmaf(wv3.y, h2.y, p11);
        p20 = fmaf(wv3.z, h2.x, p20); p21 = fmaf(wv3.z, h2.y, p21);
        p30 = fmaf(wv3.w, h2.x, p30); p31 = fmaf(wv3.w, h2.y, p31);
    }

    // ---------------- Per-warp write-back ----------------
    sRed[warp][0][lane] = p00; sRed[warp][0][lane+32] = p01;
    sRed[warp][1][lane] = p10; sRed[warp][1][lane+32] = p11;
    sRed[warp][2][lane] = p20; sRed[warp][2][lane+32] = p21;
    sRed[warp][3][lane] = p30; sRed[warp][3][lane+32] = p31;
    sOwn += __shfl_xor_sync(0xffffffffu, sOwn, 1);
    sOwn += __shfl_xor_sync(0xffffffffu, sOwn, 2);
    sOwn += __shfl_xor_sync(0xffffffffu, sOwn, 4);
    if (s == 0) sWsum[warp][h] = sOwn * 0.5f;   // dedupe the s / s+4 duplication
    __syncthreads();

    // ---------------- Finalize: normalize, @enc_w2, output MLP ----------------
    if (tid < 4) {
        float ss = 0.f;
        #pragma unroll
        for (int w = 0; w < WARPS; w++) ss += sWsum[w][tid];
        sSum[tid] = ss;
    }
    __syncthreads();
    if (tid < 256) {
        const int hh = tid >> 6, j = tid & 63;
        float acc = 0.f;
        #pragma unroll
        for (int w = 0; w < WARPS; w++) acc += sRed[w][hh][j];
        sPooled[hh][j] = acc / sSum[hh];
    }
    __syncthreads();
    if (tid < 256) {
        const int hh = tid >> 6, d = tid & 63;
        float acc = enc_b2[d];
        #pragma unroll 8
        for (int k = 0; k < 64; k++)
            acc = fmaf(sPooled[hh][k], enc_w2[k*64 + d], acc);
        sCtx[hh*64 + d] = acc;     // head-major, matches reshape(B, H*HID)
    }
    __syncthreads();
    if (tid < 64) {
        float acc = out_b1[tid];
        #pragma unroll 8
        for (int c = 0; c < 256; c++)
            acc = fmaf(sCtx[c], out_w1[c*64 + tid], acc);
        sO[tid] = fmaxf(acc, 0.f);
    }
    __syncthreads();
    if (tid < 32) {
        float v = sO[tid]*out_w2[tid] + sO[tid+32]*out_w2[tid+32];
        #pragma unroll
        for (int o = 16; o > 0; o >>= 1)
            v += __shfl_xor_sync(0xffffffffu, v, o);
        if (tid == 0) out[b] = v + out_b2[0];
    }
}

extern "C" void kernel_launch(void* const* d_in, const int* in_sizes, int n_in,
                              void* d_out, int out_size)
{
    const float* radar_xy  = (const float*)d_in[0];
    const float* radar_dir = (const float*)d_in[1];
    const float* pts       = (const float*)d_in[2];
    const float* enc_w1    = (const float*)d_in[3];
    const float* enc_b1    = (const float*)d_in[4];
    const float* enc_w2    = (const float*)d_in[5];
    const float* enc_b2    = (const float*)d_in[6];
    const float* sc_w1     = (const float*)d_in[7];
    const float* sc_b1     = (const float*)d_in[8];
    const float* sc_w2     = (const float*)d_in[9];
    const float* sc_b2     = (const float*)d_in[10];
    const float* out_w1    = (const float*)d_in[11];
    const float* out_b1    = (const float*)d_in[12];
    const float* out_w2    = (const float*)d_in[13];
    const float* out_b2    = (const float*)d_in[14];
    float* out = (float*)d_out;

    mha_fused_kernel<<<Bq, THREADS>>>(
        radar_xy, radar_dir, pts,
        enc_w1, enc_b1, enc_w2, enc_b2,
        sc_w1, sc_b1, sc_w2, sc_b2,
        out_w1, out_b1, out_w2, out_b2,
        out);
}

// round 10
// speedup vs baseline: 1.9422x; 1.0015x over previous
#include <cuda_runtime.h>

// Problem constants (fixed by setup_inputs)
#define Bq      128
#define Nq      8192
#define THREADS 1024
#define WARPS   32
#define PPW     (Nq / WARPS)   // 256 points per warp
#define NBATCH  (PPW / 4)      // 64 batches of 4 points

#define LOG2E 1.4426950408889634f

typedef unsigned long long ull;

// ---- Blackwell packed fp32x2 helpers (FFMA2 only reachable via PTX) ----
static __device__ __forceinline__ ull pk2(float lo, float hi) {
    ull r; asm("mov.b64 %0, {%1, %2};" : "=l"(r) : "f"(lo), "f"(hi)); return r;
}
static __device__ __forceinline__ ull ffma2(ull a, ull b, ull c) {
    ull d; asm("fma.rn.f32x2 %0, %1, %2, %3;" : "=l"(d) : "l"(a), "l"(b), "l"(c)); return d;
}
static __device__ __forceinline__ float2 upk2(ull v) {
    float2 f; asm("mov.b64 {%0, %1}, %2;" : "=f"(f.x), "=f"(f.y) : "l"(v)); return f;
}
static __device__ __forceinline__ ull relu2(ull v) {
    float2 f = upk2(v);
    return pk2(fmaxf(f.x, 0.f), fmaxf(f.y, 0.f));
}

__global__ __launch_bounds__(THREADS, 1)
void mha_fused_kernel(const float* __restrict__ radar_xy,
                      const float* __restrict__ radar_dir,
                      const float* __restrict__ pts,
                      const float* __restrict__ enc_w1,
                      const float* __restrict__ enc_b1,
                      const float* __restrict__ enc_w2,
                      const float* __restrict__ enc_b2,
                      const float* __restrict__ sc_w1,
                      const float* __restrict__ sc_b1,
                      const float* __restrict__ sc_w2,
                      const float* __restrict__ sc_b2,
                      const float* __restrict__ out_w1,
                      const float* __restrict__ out_b1,
                      const float* __restrict__ out_w2,
                      const float* __restrict__ out_b2,
                      float* __restrict__ out)
{
    // Score-net weights packed per (k, lane=h*8+s): one LDS.128 each
    __shared__ ulonglong2 sAB[4][32];                // (a-pair px, b-pair py)
    __shared__ ulonglong2 sCV[4][32];                // (c-pair bias, v-pair w2)
    __shared__ ull        sE1p[32], sE2p[32], sBEp[32];  // encoder packed (j, j+32)
    __shared__ float4     sWexp[2][WARPS][4];        // softmax-weight broadcast (dbl buf)
    __shared__ float      sRed[WARPS][4][64];        // per-warp pooled partials
    __shared__ float      sWsum[WARPS][4];
    __shared__ float      sSum[4];
    __shared__ float      sPooled[4][64];
    __shared__ float      sCtx[256];
    __shared__ float      sO[64];

    const int b    = blockIdx.x;
    const int tid  = threadIdx.x;
    const int warp = tid >> 5;
    const int lane = tid & 31;

    const float r0 = radar_xy[b*2+0], r1 = radar_xy[b*2+1];
    const float r2 = radar_dir[b*2+0], r3 = radar_dir[b*2+1];

    // ---------------- Staging ----------------
    if (tid < 128) {
        const int k = tid >> 5, hs = tid & 31;
        const int hh = hs >> 3, j = (hs & 7) * 8 + k * 2;
        const float* w = sc_w1 + (size_t)hh * 384;
        const float c0 = sc_b1[hh*64+j]   + r0*w[j]   + r1*w[64+j]   + r2*w[128+j]   + r3*w[192+j];
        const float c1 = sc_b1[hh*64+j+1] + r0*w[j+1] + r1*w[64+j+1] + r2*w[128+j+1] + r3*w[192+j+1];
        ulonglong2 cv;
        cv.x = pk2(c0, c1);
        cv.y = pk2(sc_w2[hh*64+j], sc_w2[hh*64+j+1]);
        sCV[k][hs] = cv;
    } else if (tid < 224) {
        const int idx = tid - 128, arr = idx >> 5, l = idx & 31;
        if (arr == 0)      sE1p[l] = pk2(enc_w1[256+l], enc_w1[256+l+32]);
        else if (arr == 1) sE2p[l] = pk2(enc_w1[320+l], enc_w1[320+l+32]);
        else {
            const float b0 = enc_b1[l]    + r0*enc_w1[l]     + r1*enc_w1[64+l]
                                          + r2*enc_w1[128+l]  + r3*enc_w1[192+l];
            const float b1 = enc_b1[l+32] + r0*enc_w1[l+32]  + r1*enc_w1[64+l+32]
                                          + r2*enc_w1[128+l+32] + r3*enc_w1[192+l+32];
            sBEp[l] = pk2(b0, b1);
        }
    } else if (tid >= 256 && tid < 384) {
        const int idx = tid - 256;
        const int k = idx >> 5, hs = idx & 31;
        const int hh = hs >> 3, j = (hs & 7) * 8 + k * 2;
        const float* w = sc_w1 + (size_t)hh * 384;
        ulonglong2 ab;
        ab.x = pk2(w[256+j], w[256+j+1]);   // row 4: px coeffs
        ab.y = pk2(w[320+j], w[320+j+1]);   // row 5: py coeffs
        sAB[k][hs] = ab;
    }
    __syncthreads();

    // ---------------- Per-lane constants ----------------
    const int h = lane >> 3, s = lane & 7;
    const float b2l = sc_b2[h] * LOG2E;              // folded into exp2
    // After the butterfly, lane s holds point p(s) = (s&1)*2 + ((s>>1)&1)
    const int pOwnH = (((s & 1) << 1) + ((s >> 1) & 1)) * 4 + h;
    const bool sel1 = (s & 1) != 0, sel2 = (s & 2) != 0;

    const ull e1p = sE1p[lane], e2p = sE2p[lane], bep = sBEp[lane];

    float p00=0.f,p01=0.f,p10=0.f,p11=0.f,p20=0.f,p21=0.f,p30=0.f,p31=0.f;
    float sOwn = 0.f;

    const float4* P4 = reinterpret_cast<const float4*>(pts)
                     + (((size_t)b * Nq + (size_t)warp * PPW) >> 1);
    float* wslot = &(reinterpret_cast<float*>(&sWexp[0][warp][0]))[pOwnH];

    // ---- Stage A: logits + butterfly + exp + STS for one 4-point batch ----
    auto stageA = [&](const float4& qa, const float4& qb, int buf) {
        const ull px0 = pk2(qa.x,qa.x), py0 = pk2(qa.y,qa.y);
        const ull px1 = pk2(qa.z,qa.z), py1 = pk2(qa.w,qa.w);
        const ull px2 = pk2(qb.x,qb.x), py2 = pk2(qb.y,qb.y);
        const ull px3 = pk2(qb.z,qb.z), py3 = pk2(qb.w,qb.w);

        ull ac0, ac1, ac2, ac3;
        {
            ulonglong2 ab = sAB[0][lane];
            ulonglong2 cv = sCV[0][lane];
            ac0 = ffma2(relu2(ffma2(py0,ab.y, ffma2(px0,ab.x, cv.x))), cv.y, 0ull);
            ac1 = ffma2(relu2(ffma2(py1,ab.y, ffma2(px1,ab.x, cv.x))), cv.y, 0ull);
            ac2 = ffma2(relu2(ffma2(py2,ab.y, ffma2(px2,ab.x, cv.x))), cv.y, 0ull);
            ac3 = ffma2(relu2(ffma2(py3,ab.y, ffma2(px3,ab.x, cv.x))), cv.y, 0ull);
            ab = sAB[1][lane]; cv = sCV[1][lane];
            ac0 = ffma2(relu2(ffma2(py0,ab.y, ffma2(px0,ab.x, cv.x))), cv.y, ac0);
            ac1 = ffma2(relu2(ffma2(py1,ab.y, ffma2(px1,ab.x, cv.x))), cv.y, ac1);
            ac2 = ffma2(relu2(ffma2(py2,ab.y, ffma2(px2,ab.x, cv.x))), cv.y, ac2);
            ac3 = ffma2(relu2(ffma2(py3,ab.y, ffma2(px3,ab.x, cv.x))), cv.y, ac3);
            ab = sAB[2][lane]; cv = sCV[2][lane];
            ac0 = ffma2(relu2(ffma2(py0,ab.y, ffma2(px0,ab.x, cv.x))), cv.y, ac0);
            ac1 = ffma2(relu2(ffma2(py1,ab.y, ffma2(px1,ab.x, cv.x))), cv.y, ac1);
            ac2 = ffma2(relu2(ffma2(py2,ab.y, ffma2(px2,ab.x, cv.x))), cv.y, ac2);
            ac3 = ffma2(relu2(ffma2(py3,ab.y, ffma2(px3,ab.x, cv.x))), cv.y, ac3);
            ab = sAB[3][lane]; cv = sCV[3][lane];
            ac0 = ffma2(relu2(ffma2(py0,ab.y, ffma2(px0,ab.x, cv.x))), cv.y, ac0);
            ac1 = ffma2(relu2(ffma2(py1,ab.y, ffma2(px1,ab.x, cv.x))), cv.y, ac1);
            ac2 = ffma2(relu2(ffma2(py2,ab.y, ffma2(px2,ab.x, cv.x))), cv.y, ac2);
            ac3 = ffma2(relu2(ffma2(py3,ab.y, ffma2(px3,ab.x, cv.x))), cv.y, ac3);
        }
        float2 t;
        t = upk2(ac0); float a0 = t.x + t.y;
        t = upk2(ac1); float a1 = t.x + t.y;
        t = upk2(ac2); float a2 = t.x + t.y;
        t = upk2(ac3); float a3 = t.x + t.y;

        // batched butterfly over 8 lanes: 4 shfl / 4 points
        const float r0s = __shfl_xor_sync(0xffffffffu, sel1 ? a0 : a2, 1);
        const float r1s = __shfl_xor_sync(0xffffffffu, sel1 ? a1 : a3, 1);
        a0 = (sel1 ? a2 : a0) + r0s;
        a1 = (sel1 ? a3 : a1) + r1s;
        const float r2s = __shfl_xor_sync(0xffffffffu, sel2 ? a0 : a1, 2);
        float v = (sel2 ? a1 : a0) + r2s;
        v += __shfl_xor_sync(0xffffffffu, v, 4);

        const float w = exp2f(fmaf(v, LOG2E, b2l));
        sOwn += w;                         // each point counted twice per 8-group (x0.5 later)
        wslot[buf * (WARPS * 16)] = w;
    };

    // ---- Stage B: encoder + weighted pooling for one 4-point batch ----
    auto stageB = [&](const float4& qa, const float4& qb, int buf) {
        const float4 wv0 = sWexp[buf][warp][0];
        const float4 wv1 = sWexp[buf][warp][1];
        const float4 wv2 = sWexp[buf][warp][2];
        const float4 wv3 = sWexp[buf][warp][3];

        float2 h2;
        h2 = upk2(relu2(ffma2(pk2(qa.y,qa.y), e2p, ffma2(pk2(qa.x,qa.x), e1p, bep))));
        p00 = fmaf(wv0.x, h2.x, p00); p01 = fmaf(wv0.x, h2.y, p01);
        p10 = fmaf(wv0.y, h2.x, p10); p11 = fmaf(wv0.y, h2.y, p11);
        p20 = fmaf(wv0.z, h2.x, p20); p21 = fmaf(wv0.z, h2.y, p21);
        p30 = fmaf(wv0.w, h2.x, p30); p31 = fmaf(wv0.w, h2.y, p31);
        h2 = upk2(relu2(ffma2(pk2(qa.w,qa.w), e2p, ffma2(pk2(qa.z,qa.z), e1p, bep))));
        p00 = fmaf(wv1.x, h2.x, p00); p01 = fmaf(wv1.x, h2.y, p01);
        p10 = fmaf(wv1.y, h2.x, p10); p11 = fmaf(wv1.y, h2.y, p11);
        p20 = fmaf(wv1.z, h2.x, p20); p21 = fmaf(wv1.z, h2.y, p21);
        p30 = fmaf(wv1.w, h2.x, p30); p31 = fmaf(wv1.w, h2.y, p31);
        h2 = upk2(relu2(ffma2(pk2(qb.y,qb.y), e2p, ffma2(pk2(qb.x,qb.x), e1p, bep))));
        p00 = fmaf(wv2.x, h2.x, p00); p01 = fmaf(wv2.x, h2.y, p01);
        p10 = fmaf(wv2.y, h2.x, p10); p11 = fmaf(wv2.y, h2.y, p11);
        p20 = fmaf(wv2.z, h2.x, p20); p21 = fmaf(wv2.z, h2.y, p21);
        p30 = fmaf(wv2.w, h2.x, p30); p31 = fmaf(wv2.w, h2.y, p31);
        h2 = upk2(relu2(ffma2(pk2(qb.w,qb.w), e2p, ffma2(pk2(qb.z,qb.z), e1p, bep))));
        p00 = fmaf(wv3.x, h2.x, p00); p01 = fmaf(wv3.x, h2.y, p01);
        p10 = fmaf(wv3.y, h2.x, p10); p11 = fmaf(wv3.y, h2.y, p11);
        p20 = fmaf(wv3.z, h2.x, p20); p21 = fmaf(wv3.z, h2.y, p21);
        p30 = fmaf(wv3.w, h2.x, p30); p31 = fmaf(wv3.w, h2.y, p31);
    };

    // ---------------- Software-pipelined main loop ----------------
    float4 q0c = __ldg(P4 + 0);
    float4 q1c = __ldg(P4 + 1);
    stageA(q0c, q1c, 0);                      // weights(0) -> buf 0

    #pragma unroll 1
    for (int i = 0; i < NBATCH - 1; i++) {
        const float4 qa = __ldg(P4 + 2*(i+1));
        const float4 qb = __ldg(P4 + 2*(i+1) + 1);
        stageA(qa, qb, (i+1) & 1);            // produce weights(i+1)
        __syncwarp();                          // STS(i+1) & STS(i) visible
        stageB(q0c, q1c, i & 1);              // consume weights(i)
        q0c = qa; q1c = qb;
        __syncwarp();                          // protect buf (i) from STS(i+2) overwrite
    }
    stageB(q0c, q1c, (NBATCH - 1) & 1);       // epilogue: consume last weights

    // ---------------- Per-warp write-back ----------------
    sRed[warp][0][lane] = p00; sRed[warp][0][lane+32] = p01;
    sRed[warp][1][lane] = p10; sRed[warp][1][lane+32] = p11;
    sRed[warp][2][lane] = p20; sRed[warp][2][lane+32] = p21;
    sRed[warp][3][lane] = p30; sRed[warp][3][lane+32] = p31;
    sOwn += __shfl_xor_sync(0xffffffffu, sOwn, 1);
    sOwn += __shfl_xor_sync(0xffffffffu, sOwn, 2);
    sOwn += __shfl_xor_sync(0xffffffffu, sOwn, 4);
    if (s == 0) sWsum[warp][h] = sOwn * 0.5f;   // dedupe the s / s+4 duplication
    __syncthreads();

    // ---------------- Finalize: normalize, @enc_w2, output MLP ----------------
    if (tid < 4) {
        float ss = 0.f;
        #pragma unroll
        for (int w = 0; w < WARPS; w++) ss += sWsum[w][tid];
        sSum[tid] = ss;
    }
    __syncthreads();
    if (tid < 256) {
        const int hh = tid >> 6, j = tid & 63;
        float acc = 0.f;
        #pragma unroll
        for (int w = 0; w < WARPS; w++) acc += sRed[w][hh][j];
        sPooled[hh][j] = acc / sSum[hh];
    }
    __syncthreads();
    if (tid < 256) {
        const int hh = tid >> 6, d = tid & 63;
        float acc = enc_b2[d];
        #pragma unroll 8
        for (int k = 0; k < 64; k++)
            acc = fmaf(sPooled[hh][k], enc_w2[k*64 + d], acc);
        sCtx[hh*64 + d] = acc;     // head-major, matches reshape(B, H*HID)
    }
    __syncthreads();
    if (tid < 64) {
        float acc = out_b1[tid];
        #pragma unroll 8
        for (int c = 0; c < 256; c++)
            acc = fmaf(sCtx[c], out_w1[c*64 + tid], acc);
        sO[tid] = fmaxf(acc, 0.f);
    }
    __syncthreads();
    if (tid < 32) {
        float v = sO[tid]*out_w2[tid] + sO[tid+32]*out_w2[tid+32];
        #pragma unroll
        for (int o = 16; o > 0; o >>= 1)
            v += __shfl_xor_sync(0xffffffffu, v, o);
        if (tid == 0) out[b] = v + out_b2[0];
    }
}

extern "C" void kernel_launch(void* const* d_in, const int* in_sizes, int n_in,
                              void* d_out, int out_size)
{
    const float* radar_xy  = (const float*)d_in[0];
    const float* radar_dir = (const float*)d_in[1];
    const float* pts       = (const float*)d_in[2];
    const float* enc_w1    = (const float*)d_in[3];
    const float* enc_b1    = (const float*)d_in[4];
    const float* enc_w2    = (const float*)d_in[5];
    const float* enc_b2    = (const float*)d_in[6];
    const float* sc_w1     = (const float*)d_in[7];
    const float* sc_b1     = (const float*)d_in[8];
    const float* sc_w2     = (const float*)d_in[9];
    const float* sc_b2     = (const float*)d_in[10];
    const float* out_w1    = (const float*)d_in[11];
    const float* out_b1    = (const float*)d_in[12];
    const float* out_w2    = (const float*)d_in[13];
    const float* out_b2    = (const float*)d_in[14];
    float* out = (float*)d_out;

    mha_fused_kernel<<<Bq, THREADS>>>(
        radar_xy, radar_dir, pts,
        enc_w1, enc_b1, enc_w2, enc_b2,
        sc_w1, sc_b1, sc_w2, sc_b2,
        out_w1, out_b1, out_w2, out_b2,
        out);
}